// round 1
// baseline (speedup 1.0000x reference)
#include <cuda_runtime.h>
#include <math.h>

#define BB 16
#define EE 4
#define DIMC 64
#define RR 32
#define HH 128
#define WW 128
#define HWPX (HH*WW)
#define FREQN 64
#define NPAIR (BB*EE)

// ---------------- scratch (device globals; no allocation allowed) ----------------
__device__ float d_pooled[BB][DIMC];
__device__ float d_gates[BB][EE];
__device__ float d_gatesum[BB];
__device__ int   d_topidx[BB][2];
__device__ float d_qc[EE][RR][DIMC];        // q_w @ p0 composed
__device__ float d_kvc[EE][2*RR][DIMC];     // kv_w @ p0 composed
__device__ float d_qpre[NPAIR][RR][HWPX];
__device__ float d_kvpre[NPAIR][2*RR][HWPX];
__device__ float d_qb[NPAIR][RR][HWPX];
__device__ float d_kb[NPAIR][RR][HWPX];
__device__ float d_vb[NPAIR][RR][HWPX];
__device__ float d_gact[NPAIR][RR][HWPX];   // silu(p1 @ shared)
__device__ float d_attb[NPAIR][RR][HWPX];   // after po conv

// ---------------- K0: pooled mean over H,W ----------------
__global__ void k_pool(const float* __restrict__ x) {
    int bc = blockIdx.x;                    // b*DIMC + c
    const float* p = x + (size_t)bc * HWPX;
    float s = 0.f;
    for (int i = threadIdx.x; i < HWPX; i += 256) s += p[i];
    __shared__ float sm[256];
    sm[threadIdx.x] = s;
    __syncthreads();
    for (int o = 128; o > 0; o >>= 1) {
        if (threadIdx.x < o) sm[threadIdx.x] += sm[threadIdx.x + o];
        __syncthreads();
    }
    if (threadIdx.x == 0) d_pooled[bc / DIMC][bc % DIMC] = sm[0] * (1.f / (float)HWPX);
}

// ---------------- K1: gating (softmax + top-2) ----------------
__global__ void k_gate(const float* __restrict__ freq_emb, const float* __restrict__ noise,
                       const float* __restrict__ gate_w, const float* __restrict__ fgw) {
    int b = threadIdx.x;
    if (b >= BB) return;
    float lg[EE];
    for (int e = 0; e < EE; e++) {
        float s = 0.f;
        for (int d = 0; d < DIMC; d++) s += d_pooled[b][d] * gate_w[e * DIMC + d];
        for (int f = 0; f < FREQN; f++) s += freq_emb[b * FREQN + f] * fgw[e * FREQN + f];
        lg[e] = s + noise[b * EE + e] * (1.0f / (float)EE);
    }
    float mx = lg[0];
    for (int e = 1; e < EE; e++) mx = fmaxf(mx, lg[e]);
    float se = 0.f, sc[EE];
    for (int e = 0; e < EE; e++) { sc[e] = expf(lg[e] - mx); se += sc[e]; }
    for (int e = 0; e < EE; e++) sc[e] /= se;
    // top-2, stable (earliest index wins on ties, matches jax.lax.top_k)
    int i1 = 0;
    for (int e = 1; e < EE; e++) if (sc[e] > sc[i1]) i1 = e;
    int i2 = -1;
    for (int e = 0; e < EE; e++) {
        if (e == i1) continue;
        if (i2 < 0 || sc[e] > sc[i2]) i2 = e;
    }
    for (int e = 0; e < EE; e++) d_gates[b][e] = (e == i1 || e == i2) ? sc[e] : 0.f;
    d_gatesum[b] = sc[i1] + sc[i2];
    d_topidx[b][0] = i1;
    d_topidx[b][1] = i2;
}

// ---------------- K2: compose q_w@p0, kv_w@p0 ----------------
__global__ void k_compose(const float* __restrict__ p0, const float* __restrict__ q_w,
                          const float* __restrict__ kv_w) {
    int e = blockIdx.x;
    __shared__ float sp0[RR][DIMC];
    for (int i = threadIdx.x; i < RR * DIMC; i += 256)
        sp0[i / DIMC][i % DIMC] = p0[e * RR * DIMC + i];
    __syncthreads();
    for (int i = threadIdx.x; i < RR * DIMC; i += 256) {
        int o = i / DIMC, d = i % DIMC;
        float s = 0.f;
        for (int c = 0; c < RR; c++) s += q_w[(e * RR + o) * RR + c] * sp0[c][d];
        d_qc[e][o][d] = s;
    }
    for (int i = threadIdx.x; i < 2 * RR * DIMC; i += 256) {
        int o = i / DIMC, d = i % DIMC;
        float s = 0.f;
        for (int c = 0; c < RR; c++) s += kv_w[(e * 2 * RR + o) * RR + c] * sp0[c][d];
        d_kvc[e][o][d] = s;
    }
}

// ---------------- K3: per-pixel matmuls: qpre/kvpre from x, silu-gate from shared ----------------
__global__ __launch_bounds__(256) void k_pre(const float* __restrict__ x,
                                             const float* __restrict__ shin,
                                             const float* __restrict__ p1) {
    int pair = blockIdx.y;
    int b = pair / EE, e = pair % EE;
    if (d_gates[b][e] == 0.f) return;

    __shared__ float wq[RR][DIMC];
    __shared__ float wkv[2 * RR][DIMC];
    __shared__ float wp1[RR][DIMC];
    for (int i = threadIdx.x; i < RR * DIMC; i += 256) wq[i / DIMC][i % DIMC] = d_qc[e][i / DIMC][i % DIMC];
    for (int i = threadIdx.x; i < 2 * RR * DIMC; i += 256) wkv[i / DIMC][i % DIMC] = d_kvc[e][i / DIMC][i % DIMC];
    for (int i = threadIdx.x; i < RR * DIMC; i += 256) wp1[i / DIMC][i % DIMC] = p1[e * RR * DIMC + i];
    __syncthreads();

    int p = blockIdx.x * 256 + threadIdx.x;
    float xv[DIMC];
    const float* xb = x + (size_t)b * DIMC * HWPX + p;
#pragma unroll
    for (int d = 0; d < DIMC; d++) xv[d] = xb[(size_t)d * HWPX];

    for (int o = 0; o < RR; o++) {
        float s = 0.f;
#pragma unroll
        for (int d = 0; d < DIMC; d++) s += wq[o][d] * xv[d];
        d_qpre[pair][o][p] = s;
    }
    for (int o = 0; o < 2 * RR; o++) {
        float s = 0.f;
#pragma unroll
        for (int d = 0; d < DIMC; d++) s += wkv[o][d] * xv[d];
        d_kvpre[pair][o][p] = s;
    }
    const float* sb = shin + (size_t)b * DIMC * HWPX + p;
#pragma unroll
    for (int d = 0; d < DIMC; d++) xv[d] = sb[(size_t)d * HWPX];
    for (int o = 0; o < RR; o++) {
        float s = 0.f;
#pragma unroll
        for (int d = 0; d < DIMC; d++) s += wp1[o][d] * xv[d];
        d_gact[pair][o][p] = s / (1.f + expf(-s));   // silu
    }
}

// ---------------- K4: depthwise conv (3x3 on q, 7x7 on kv) ----------------
__global__ void k_dw(const float* __restrict__ q_dw, const float* __restrict__ kv_dw) {
    int pair = blockIdx.z;
    int b = pair / EE, e = pair % EE;
    if (d_gates[b][e] == 0.f) return;
    int ch = blockIdx.y;                     // 0..31 = q(3x3), 32..95 = kv(7x7)
    int ty = (blockIdx.x / 8) * 16, tx = (blockIdx.x % 8) * 16;
    bool isq = ch < RR;
    int r = isq ? 1 : 3;
    int ks = 2 * r + 1;
    int tw = 16 + 2 * r;
    const float* src = isq ? &d_qpre[pair][ch][0] : &d_kvpre[pair][ch - RR][0];
    const float* w = isq ? q_dw + (size_t)(e * RR + ch) * 9
                         : kv_dw + (size_t)(e * 2 * RR + (ch - RR)) * 49;

    __shared__ float tile[22 * 22];
    __shared__ float ws[49];
    if (threadIdx.x < ks * ks) ws[threadIdx.x] = w[threadIdx.x];
    for (int i = threadIdx.x; i < tw * tw; i += 256) {
        int iy = i / tw, ix = i % tw;
        int gy = ty + iy - r, gx = tx + ix - r;
        tile[i] = (gy >= 0 && gy < HH && gx >= 0 && gx < WW) ? src[gy * WW + gx] : 0.f;
    }
    __syncthreads();
    int ly = threadIdx.x / 16, lx = threadIdx.x % 16;
    float s = 0.f;
    for (int dy = 0; dy < ks; dy++)
        for (int dx = 0; dx < ks; dx++)
            s += tile[(ly + dy) * tw + lx + dx] * ws[dy * ks + dx];
    float* dst;
    if (isq) dst = &d_qb[pair][ch][0];
    else if (ch < 2 * RR) dst = &d_kb[pair][ch - RR][0];
    else dst = &d_vb[pair][ch - 2 * RR][0];
    dst[(ty + ly) * WW + tx + lx] = s;
}

// ---------------- K5: per-patch 8x8 circular conv + LN + *v + po conv ----------------
__global__ __launch_bounds__(256) void k_patch(const float* __restrict__ ln_w,
                                               const float* __restrict__ ln_b,
                                               const float* __restrict__ po_w,
                                               const float* __restrict__ po_b) {
    int pair = blockIdx.y;
    int b = pair / EE, e = pair % EE;
    if (d_gates[b][e] == 0.f) return;
    int patch = blockIdx.x;
    int pi = patch / 16, pj = patch % 16;
    int r0 = pi * 8, c0 = pj * 8;
    int t = threadIdx.x;

    __shared__ float sq[RR][64];   // q patch -> later circular-conv result
    __shared__ float sk[RR][64];   // k patch -> later (LN * v) result
    __shared__ float spw[RR][RR];
    __shared__ float spb[RR], slw[RR], slb[RR];

    // loads
    for (int i = t; i < RR * 64; i += 256) {
        int c = i >> 6, pix = i & 63;
        int gi = r0 + (pix >> 3), gj = c0 + (pix & 7);
        sq[c][pix] = d_qb[pair][c][gi * WW + gj];
        sk[c][pix] = d_kb[pair][c][gi * WW + gj];
    }
    for (int i = t; i < RR * RR; i += 256) spw[i / RR][i % RR] = po_w[(size_t)e * RR * RR + i];
    if (t < RR) {
        spb[t] = po_b[e * RR + t];
        slw[t] = ln_w[e * RR + t];
        slb[t] = ln_b[e * RR + t];
    }
    __syncthreads();

    // 8x8 circular conv per channel: out[i,j] = sum_{u,v} q[u,v] k[(i-u)&7,(j-v)&7]
    float tmp[8];
#pragma unroll
    for (int kk = 0; kk < 8; kk++) {
        int oidx = kk * 256 + t;
        int c = oidx >> 6, pix = oidx & 63;
        int i = pix >> 3, j = pix & 7;
        float s = 0.f;
#pragma unroll
        for (int u = 0; u < 8; u++) {
            int iu = (i - u) & 7;
#pragma unroll
            for (int v = 0; v < 8; v++)
                s += sq[c][u * 8 + v] * sk[c][iu * 8 + ((j - v) & 7)];
        }
        tmp[kk] = s;
    }
    __syncthreads();
#pragma unroll
    for (int kk = 0; kk < 8; kk++) {
        int oidx = kk * 256 + t;
        sq[oidx >> 6][oidx & 63] = tmp[kk];   // conv result now in sq
    }
    __syncthreads();

    // LayerNorm over channels per pixel, then * v
    if (t < 64) {
        float mu = 0.f;
        for (int c = 0; c < RR; c++) mu += sq[c][t];
        mu *= (1.f / RR);
        float var = 0.f;
        for (int c = 0; c < RR; c++) { float d = sq[c][t] - mu; var += d * d; }
        var *= (1.f / RR);
        float rs = rsqrtf(var + 1e-5f);
        int gi = r0 + (t >> 3), gj = c0 + (t & 7);
        for (int c = 0; c < RR; c++) {
            float val = (sq[c][t] - mu) * rs * slw[c] + slb[c];
            sk[c][t] = val * d_vb[pair][c][gi * WW + gj];
        }
    }
    __syncthreads();

    // po conv (32->32) per pixel
#pragma unroll
    for (int kk = 0; kk < 8; kk++) {
        int oidx = kk * 256 + t;
        int o = oidx >> 6, pix = oidx & 63;
        float s = spb[o];
#pragma unroll
        for (int c = 0; c < RR; c++) s += spw[o][c] * sk[c][pix];
        int gi = r0 + (pix >> 3), gj = c0 + (pix & 7);
        d_attb[pair][o][gi * WW + gj] = s;
    }
}

// ---------------- K6: out = gatesum*x + sum_e gate * p2 @ (att * g) ----------------
__global__ __launch_bounds__(256) void k_out(const float* __restrict__ x,
                                             const float* __restrict__ p2,
                                             float* __restrict__ out) {
    int b = blockIdx.y;
    __shared__ float sp2[2][DIMC][RR];
    int e1 = d_topidx[b][0], e2 = d_topidx[b][1];
    float g1 = d_gates[b][e1], g2 = d_gates[b][e2];
    for (int i = threadIdx.x; i < DIMC * RR; i += 256) {
        sp2[0][i / RR][i % RR] = p2[(size_t)e1 * DIMC * RR + i];
        sp2[1][i / RR][i % RR] = p2[(size_t)e2 * DIMC * RR + i];
    }
    __syncthreads();

    int p = blockIdx.x * 256 + threadIdx.x;
    int pr1 = b * EE + e1, pr2 = b * EE + e2;
    float av0[RR], av1[RR];
#pragma unroll
    for (int c = 0; c < RR; c++) av0[c] = g1 * d_attb[pr1][c][p] * d_gact[pr1][c][p];
#pragma unroll
    for (int c = 0; c < RR; c++) av1[c] = g2 * d_attb[pr2][c][p] * d_gact[pr2][c][p];

    float gs = d_gatesum[b];
    const float* xb = x + (size_t)b * DIMC * HWPX;
    float* ob = out + (size_t)b * DIMC * HWPX;
    for (int o = 0; o < DIMC; o++) {
        float s = gs * xb[(size_t)o * HWPX + p];
#pragma unroll
        for (int c = 0; c < RR; c++) s += sp2[0][o][c] * av0[c] + sp2[1][o][c] * av1[c];
        ob[(size_t)o * HWPX + p] = s;
    }
}

// ---------------- launch ----------------
extern "C" void kernel_launch(void* const* d_in, const int* in_sizes, int n_in,
                              void* d_out, int out_size) {
    const float* x      = (const float*)d_in[0];
    const float* shin   = (const float*)d_in[1];
    const float* femb   = (const float*)d_in[2];
    const float* noise  = (const float*)d_in[3];
    const float* gate_w = (const float*)d_in[4];
    const float* fgw    = (const float*)d_in[5];
    const float* p0     = (const float*)d_in[6];
    const float* p1     = (const float*)d_in[7];
    const float* p2     = (const float*)d_in[8];
    const float* q_w    = (const float*)d_in[9];
    const float* q_dw   = (const float*)d_in[10];
    const float* kv_w   = (const float*)d_in[11];
    const float* kv_dw  = (const float*)d_in[12];
    const float* ln_w   = (const float*)d_in[13];
    const float* ln_b   = (const float*)d_in[14];
    const float* po_w   = (const float*)d_in[15];
    const float* po_b   = (const float*)d_in[16];
    float* out = (float*)d_out;

    k_pool<<<BB * DIMC, 256>>>(x);
    k_gate<<<1, 32>>>(femb, noise, gate_w, fgw);
    k_compose<<<EE, 256>>>(p0, q_w, kv_w);
    k_pre<<<dim3(HWPX / 256, NPAIR), 256>>>(x, shin, p1);
    k_dw<<<dim3(64, 96, NPAIR), 256>>>(q_dw, kv_dw);
    k_patch<<<dim3(256, NPAIR), 256>>>(ln_w, ln_b, po_w, po_b);
    k_out<<<dim3(HWPX / 256, BB), 256>>>(x, p2, out);
}